// round 14
// baseline (speedup 1.0000x reference)
#include <cuda_runtime.h>
#include <cuda_bf16.h>
#include <stdint.h>

#define B_ 64
#define F_ 4
#define V_ 256
#define D_ 16384
#define ITERS_ 10
#define KCH 32               // split-K chunks for stage 2
#define KC (D_/KCH)          // 512 k per chunk

// ---------------- static device scratch (no runtime allocation) ----------------
__device__ __align__(16) __nv_bfloat16 g_in_bf [B_*D_];                 // input, +-1 bf16
__device__ __align__(16) __nv_bfloat16 g_est_bf[B_*F_*D_];              // current estimates, +-1 bf16
__device__ __align__(16) __nv_bfloat16 g_cbK   [(size_t)F_*V_*D_];      // codebook [f][v][d] bf16
__device__ __align__(16) __nv_bfloat16 g_cbD   [(size_t)F_*D_*V_];      // codebook [f][d][v] bf16
__device__ __align__(16) float         g_simp  [(size_t)KCH*F_*B_*V_];  // split-K partials
__device__ __align__(16) float         g_sim   [F_*B_*V_];              // reduced sim (exact ints)
__device__ __align__(16) __nv_bfloat16 g_Ah    [F_*B_*V_];              // sim & ~127 (exact bf16)
__device__ __align__(16) __nv_bfloat16 g_Al    [F_*B_*V_];              // sim &  127 (exact bf16)

// ---------------- mma.sync helper (bf16, fp32 accum — exact for our integer data) ----
__device__ __forceinline__ void mma16816(float c[4], const uint32_t a[4], const uint32_t b[2]) {
    asm volatile(
        "mma.sync.aligned.m16n8k16.row.col.f32.bf16.bf16.f32 "
        "{%0,%1,%2,%3},{%4,%5,%6,%7},{%8,%9},{%0,%1,%2,%3};\n"
        : "+f"(c[0]), "+f"(c[1]), "+f"(c[2]), "+f"(c[3])
        : "r"(a[0]), "r"(a[1]), "r"(a[2]), "r"(a[3]), "r"(b[0]), "r"(b[1]));
}

__device__ __forceinline__ void ldsm_x4(uint32_t& r0, uint32_t& r1, uint32_t& r2, uint32_t& r3,
                                        uint32_t saddr) {
    asm volatile("ldmatrix.sync.aligned.m8n8.x4.shared.b16 {%0,%1,%2,%3}, [%4];"
                 : "=r"(r0), "=r"(r1), "=r"(r2), "=r"(r3) : "r"(saddr));
}

// ---------------- setup: input + est signs in ONE launch ----------------
#define NPAIRS_IN  (B_*D_/2)        // 524288
#define NPAIRS_EST (B_*F_*D_/2)     // 2097152
__global__ void k_signs(const float* __restrict__ input, const float* __restrict__ est0) {
    int i = blockIdx.x * blockDim.x + threadIdx.x;
    if (i < NPAIRS_IN) {
        uint2 u = ((const uint2*)input)[i];
        ((uint32_t*)g_in_bf)[i] = 0x3F803F80u | ((u.x >> 16) & 0x8000u) | (u.y & 0x80000000u);
    } else {
        int j = i - NPAIRS_IN;
        if (j < NPAIRS_EST) {
            uint2 u = ((const uint2*)est0)[j];
            ((uint32_t*)g_est_bf)[j] = 0x3F803F80u | ((u.x >> 16) & 0x8000u) | (u.y & 0x80000000u);
        }
    }
}

// ---------------- setup: codebook -> bf16, both layouts, single fp32 read -------------
__global__ void k_cb(const float* __restrict__ cb) {
    __shared__ unsigned short ts[32][33];
    int f = blockIdx.z, d0 = blockIdx.x * 32, v0 = blockIdx.y * 32;
    int tx = threadIdx.x & 31, ty = threadIdx.x >> 5;  // 32 x 8
#pragma unroll
    for (int r = 0; r < 4; r++) {
        int v = v0 + ty + r * 8;
        uint32_t ub = __float_as_uint(cb[((size_t)(f * V_ + v)) * D_ + d0 + tx]);
        unsigned short s = (unsigned short)(0x3F80u | ((ub >> 16) & 0x8000u));
        ts[ty + r * 8][tx] = s;
        ((unsigned short*)g_cbK)[((size_t)(f * V_ + v)) * D_ + d0 + tx] = s;   // row-major
    }
    __syncthreads();
#pragma unroll
    for (int r = 0; r < 4; r++) {
        int d = d0 + ty + r * 8;
        ((unsigned short*)g_cbD)[((size_t)(f * D_ + d)) * V_ + v0 + tx] = ts[tx][ty + r * 8];
    }
}

// ---------------- nop kernel: pads launch order so ncu (-s) captures k_sim ------------
__global__ void k_nop() { }

// ---------------- stage 2: sim[f][b][v] = sum_d n * cb -------------------------------
// grid (KCH, F, 2): each CTA computes 128 of 256 v with 256 threads / 27KB smem.
// 2 independent CTAs co-reside per SM -> cross-CTA latency hiding (no shared barrier).
// mode 0: n = input * prod(est) * est_f inline (6-word XOR); mode 1: n = est_f.
__global__ void __launch_bounds__(256) k_sim(int mode) {
    __shared__ __align__(16) __nv_bfloat16 As[64 * 72];    // 64 x 64 k
    __shared__ __align__(16) __nv_bfloat16 Bs[128 * 72];   // 128 v x 64 k
    const int kc = blockIdx.x, f = blockIdx.y;
    const int vhalf = blockIdx.z * 128;
    const int tid = threadIdx.x;
    const int w = tid >> 5, lane = tid & 31, g = lane >> 2, t = lane & 3;
    const int arow = tid >> 2, aseg = tid & 3;       // A: 64 rows x 4 seg-pairs (2 uint4 each)
    const int vB = tid >> 3, chB = tid & 7;          // B: 32 rows/pass x 8 segments

    const uint4* pin = (const uint4*)(g_in_bf + (size_t)arow * D_);
    const uint4* pef = (const uint4*)(g_est_bf + ((size_t)arow * F_ + f) * D_);

    const uint32_t asBase = (uint32_t)__cvta_generic_to_shared(As);
    const uint32_t bsBase = (uint32_t)__cvta_generic_to_shared(Bs);
    const int laneRow  = lane & 15;
    const int laneColH = (lane >> 4) & 1;

    float acc[4][2][4];
#pragma unroll
    for (int mt = 0; mt < 4; mt++)
#pragma unroll
        for (int nt = 0; nt < 2; nt++)
#pragma unroll
            for (int j = 0; j < 4; j++) acc[mt][nt][j] = 0.f;

    uint4 a0, a1;                              // final A words (prefetched+computed)
    uint4 rB[4];                               // B prefetch regs

    // ---- A fetch/compute of ONE uint4 at uint4-index ai (R7-proven 6-word XOR) ----
    auto fetchA = [&](int ai) -> uint4 {
        if (mode == 0) {
            uint4 x0 = pin[ai];
            uint4 f0 = make_uint4(0, 0, 0, 0);
#pragma unroll
            for (int ff = 0; ff < F_; ff++) {
                const uint4* pe = (const uint4*)(g_est_bf + ((size_t)arow * F_ + ff) * D_);
                uint4 e0 = pe[ai];
                x0.x ^= e0.x; x0.y ^= e0.y; x0.z ^= e0.z; x0.w ^= e0.w;
                if (ff == f) f0 = e0;
            }
            // est_f appears twice (total product and unbound factor) -> xor again
            x0.x ^= f0.x; x0.y ^= f0.y; x0.z ^= f0.z; x0.w ^= f0.w;
            // 6 valid +-1 bf16 words XORed -> magnitude bits cancel; restore
            uint4 o;
            o.x = 0x3F803F80u ^ x0.x; o.y = 0x3F803F80u ^ x0.y;
            o.z = 0x3F803F80u ^ x0.z; o.w = 0x3F803F80u ^ x0.w;
            return o;
        } else {
            return pef[ai];
        }
    };

    // preload ks=0
    {
        const int k0 = kc * KC;
        const int ai0 = (k0 >> 3) + aseg * 2;
        a0 = fetchA(ai0); a1 = fetchA(ai0 + 1);
#pragma unroll
        for (int p = 0; p < 4; p++) {
            int v = vhalf + p * 32 + vB;
            rB[p] = *(const uint4*)(g_cbK + ((size_t)(f * V_ + v)) * D_ + k0 + chB * 8);
        }
    }

    for (int ks = 0; ks < KC / 64; ks++) {
        // ---- store current tile from regs ----
        {
            uint4* as = (uint4*)((uint32_t*)As + arow * 36 + aseg * 8);
            as[0] = a0; as[1] = a1;
#pragma unroll
            for (int p = 0; p < 4; p++)
                *(uint4*)((uint32_t*)Bs + (p * 32 + vB) * 36 + chB * 4) = rB[p];
        }
        __syncthreads();

        // ---- prefetch next tile (overlapped with mma below) ----
        if (ks + 1 < KC / 64) {
            const int k0n = kc * KC + (ks + 1) * 64;
            const int ai0 = (k0n >> 3) + aseg * 2;
            a0 = fetchA(ai0); a1 = fetchA(ai0 + 1);
#pragma unroll
            for (int p = 0; p < 4; p++) {
                int v = vhalf + p * 32 + vB;
                rB[p] = *(const uint4*)(g_cbK + ((size_t)(f * V_ + v)) * D_ + k0n + chB * 8);
            }
        }

        // ---- mma over 4 k16 steps (ldmatrix fragments; proven patterns) ----
#pragma unroll
        for (int k16 = 0; k16 < 4; k16++) {
            const int colElem = k16 * 16 + laneColH * 8;
            uint32_t a[4][4], b[2][2];
#pragma unroll
            for (int mt = 0; mt < 4; mt++) {
                uint32_t ad = asBase + ((mt * 16 + laneRow) * 72 + colElem) * 2;
                ldsm_x4(a[mt][0], a[mt][1], a[mt][2], a[mt][3], ad);
            }
            {
                uint32_t bd = bsBase + ((w * 16 + laneRow) * 72 + colElem) * 2;
                ldsm_x4(b[0][0], b[1][0], b[0][1], b[1][1], bd);
            }
#pragma unroll
            for (int mt = 0; mt < 4; mt++)
#pragma unroll
                for (int nt = 0; nt < 2; nt++) mma16816(acc[mt][nt], a[mt], b[nt]);
        }
        __syncthreads();
    }
    // --- write split-K partials (c-ranges disjoint across blockIdx.z) ---
    float* op = g_simp + ((size_t)(kc * F_ + f) * B_) * V_;
#pragma unroll
    for (int mt = 0; mt < 4; mt++) {
        int r = mt * 16 + g;
#pragma unroll
        for (int nt = 0; nt < 2; nt++) {
            int c = vhalf + w * 16 + nt * 8 + 2 * t;
            *(float2*)&op[(size_t)r * V_ + c]       = make_float2(acc[mt][nt][0], acc[mt][nt][1]);
            *(float2*)&op[(size_t)(r + 8) * V_ + c] = make_float2(acc[mt][nt][2], acc[mt][nt][3]);
        }
    }
}

// ---------------- reduce partials: 2 threads/element + shfl ----------------
__global__ void k_reduce() {
    int gid = blockIdx.x * blockDim.x + threadIdx.x;    // 131072 threads
    int i = gid >> 1;                                   // element 0..65535
    int half = gid & 1;
    float s = 0.f;
#pragma unroll
    for (int j = 0; j < KCH / 2; j++)
        s += g_simp[(size_t)(half * (KCH / 2) + j) * (F_ * B_ * V_) + i];
    s += __shfl_xor_sync(0xffffffffu, s, 1);            // pair lanes 2k / 2k+1
    if (half == 0) {
        g_sim[i] = s;
        int si = (int)s;                                // exact integer
        g_Ah[i] = __float2bfloat16((float)(si & ~127)); // multiple of 128 -> exact bf16
        g_Al[i] = __float2bfloat16((float)(si & 127));  // 0..127 -> exact bf16
    }
}

// ---------------- stage 3: est = sign( sum_v sim * cbD ) ----------------
__global__ void __launch_bounds__(256) k_update() {
    __shared__ __align__(16) __nv_bfloat16 Bs[128 * 72];
    __shared__ __align__(16) __nv_bfloat16 Ahs[64 * 72];
    __shared__ __align__(16) __nv_bfloat16 Als[64 * 72];
    const int dt = blockIdx.x, f = blockIdx.y;
    const int d0 = dt * 128;
    const int tid = threadIdx.x;
    const int w = tid >> 5, lane = tid & 31, g = lane >> 2, t = lane & 3;
    const int arow = tid >> 2, aseg = tid & 3;
    const int dB = tid >> 3, chB = tid & 7;

    const uint32_t ahBase = (uint32_t)__cvta_generic_to_shared(Ahs);
    const uint32_t alBase = (uint32_t)__cvta_generic_to_shared(Als);
    const uint32_t bsBase = (uint32_t)__cvta_generic_to_shared(Bs);
    const int laneRow  = lane & 15;
    const int laneColH = (lane >> 4) & 1;

    float acc[4][2][4];
#pragma unroll
    for (int mt = 0; mt < 4; mt++)
#pragma unroll
        for (int nt = 0; nt < 2; nt++)
#pragma unroll
            for (int j = 0; j < 4; j++) acc[mt][nt][j] = 0.f;

    uint4 h0, h1, l0, l1;
    uint4 rB[4];
    {
        const int vv = aseg * 16;
        h0 = *(const uint4*)(g_Ah + ((size_t)f * B_ + arow) * V_ + vv);
        h1 = *(const uint4*)(g_Ah + ((size_t)f * B_ + arow) * V_ + vv + 8);
        l0 = *(const uint4*)(g_Al + ((size_t)f * B_ + arow) * V_ + vv);
        l1 = *(const uint4*)(g_Al + ((size_t)f * B_ + arow) * V_ + vv + 8);
#pragma unroll
        for (int p = 0; p < 4; p++) {
            int dl = p * 32 + dB;
            rB[p] = *(const uint4*)(g_cbD + ((size_t)(f * D_ + d0 + dl)) * V_ + chB * 8);
        }
    }

    for (int vs = 0; vs < 4; vs++) {
        {
            uint4* ah = (uint4*)((uint32_t*)Ahs + arow * 36 + aseg * 8);
            uint4* al = (uint4*)((uint32_t*)Als + arow * 36 + aseg * 8);
            ah[0] = h0; ah[1] = h1;
            al[0] = l0; al[1] = l1;
#pragma unroll
            for (int p = 0; p < 4; p++)
                *(uint4*)((uint32_t*)Bs + (p * 32 + dB) * 36 + chB * 4) = rB[p];
        }
        __syncthreads();

        if (vs + 1 < 4) {
            const int v0n = (vs + 1) * 64;
            const int vv = v0n + aseg * 16;
            h0 = *(const uint4*)(g_Ah + ((size_t)f * B_ + arow) * V_ + vv);
            h1 = *(const uint4*)(g_Ah + ((size_t)f * B_ + arow) * V_ + vv + 8);
            l0 = *(const uint4*)(g_Al + ((size_t)f * B_ + arow) * V_ + vv);
            l1 = *(const uint4*)(g_Al + ((size_t)f * B_ + arow) * V_ + vv + 8);
#pragma unroll
            for (int p = 0; p < 4; p++) {
                int dl = p * 32 + dB;
                rB[p] = *(const uint4*)(g_cbD + ((size_t)(f * D_ + d0 + dl)) * V_ + v0n + chB * 8);
            }
        }

#pragma unroll
        for (int k16 = 0; k16 < 4; k16++) {
            const int colElem = k16 * 16 + laneColH * 8;
            uint32_t fa[4][4], fl[4][4], b[2][2];
#pragma unroll
            for (int mt = 0; mt < 4; mt++) {
                uint32_t adh = ahBase + ((mt * 16 + laneRow) * 72 + colElem) * 2;
                uint32_t adl = alBase + ((mt * 16 + laneRow) * 72 + colElem) * 2;
                ldsm_x4(fa[mt][0], fa[mt][1], fa[mt][2], fa[mt][3], adh);
                ldsm_x4(fl[mt][0], fl[mt][1], fl[mt][2], fl[mt][3], adl);
            }
            {
                uint32_t bd = bsBase + ((w * 16 + laneRow) * 72 + colElem) * 2;
                ldsm_x4(b[0][0], b[1][0], b[0][1], b[1][1], bd);
            }
#pragma unroll
            for (int mt = 0; mt < 4; mt++)
#pragma unroll
                for (int nt = 0; nt < 2; nt++) {
                    mma16816(acc[mt][nt], fa[mt], b[nt]);
                    mma16816(acc[mt][nt], fl[mt], b[nt]);
                }
        }
        __syncthreads();
    }
#pragma unroll
    for (int mt = 0; mt < 4; mt++) {
        int r = mt * 16 + g;
#pragma unroll
        for (int nt = 0; nt < 2; nt++) {
            int d = d0 + w * 16 + nt * 8 + 2 * t;
            uint32_t s0 = __float_as_uint(acc[mt][nt][0]);
            uint32_t s1 = __float_as_uint(acc[mt][nt][1]);
            uint32_t s2 = __float_as_uint(acc[mt][nt][2]);
            uint32_t s3 = __float_as_uint(acc[mt][nt][3]);
            uint32_t w0 = 0x3F803F80u | ((s0 >> 16) & 0x8000u) | (s1 & 0x80000000u);
            uint32_t w1 = 0x3F803F80u | ((s2 >> 16) & 0x8000u) | (s3 & 0x80000000u);
            ((uint32_t*)g_est_bf)[(((size_t)r * F_ + f) * D_ + d) >> 1] = w0;
            ((uint32_t*)g_est_bf)[(((size_t)(r + 8) * F_ + f) * D_ + d) >> 1] = w1;
        }
    }
}

// ---------------- outputs: est emit + outcome in ONE launch ----------------
#define EMIT_BLOCKS ((B_*F_*D_/2 + 255) / 256)     // 8192
__global__ void k_out(float* __restrict__ out, int do_outcome) {
    int blk = blockIdx.x;
    if (blk < EMIT_BLOCKS) {
        int i = blk * 256 + threadIdx.x;
        if (i < B_ * F_ * D_ / 2) {
            uint32_t w = ((const uint32_t*)g_est_bf)[i];
            float2 o;
            o.x = (w & 0x8000u) ? -1.f : 1.f;
            o.y = (w & 0x80000000u) ? -1.f : 1.f;
            ((float2*)out)[i] = o;
        }
    } else if (do_outcome) {
        int warp = (blk - EMIT_BLOCKS) * 8 + (threadIdx.x >> 5);
        int lane = threadIdx.x & 31;
        if (warp >= B_ * F_) return;
        int b = warp >> 2, f = warp & 3;
        const float* s = g_sim + ((size_t)(f * B_ + b)) * V_;
        float best = -1.f; int bi = 0;
#pragma unroll
        for (int j = 0; j < 8; j++) {
            int v = j * 32 + lane;
            float a = fabsf(s[v]);
            if (a > best) { best = a; bi = v; }
        }
#pragma unroll
        for (int off = 16; off; off >>= 1) {
            float ob = __shfl_down_sync(0xffffffffu, best, off);
            int   oi = __shfl_down_sync(0xffffffffu, bi, off);
            if (ob > best || (ob == best && oi < bi)) { best = ob; bi = oi; }
        }
        if (lane == 0) out[(size_t)B_ * F_ * D_ + warp] = (float)bi;
    }
}

// ---------------- host launch ----------------
extern "C" void kernel_launch(void* const* d_in, const int* in_sizes, int n_in,
                              void* d_out, int out_size) {
    const float *input = nullptr, *est0 = nullptr, *cb = nullptr;
    for (int i = 0; i < n_in; i++) {
        if      (in_sizes[i] == B_ * D_)        input = (const float*)d_in[i];
        else if (in_sizes[i] == B_ * F_ * D_)   est0  = (const float*)d_in[i];
        else if (in_sizes[i] == F_ * V_ * D_)   cb    = (const float*)d_in[i];
    }
    if (!input && n_in > 0) input = (const float*)d_in[0];
    if (!est0  && n_in > 1) est0  = (const float*)d_in[1];
    if (!cb    && n_in > 2) cb    = (const float*)d_in[2];

    k_signs<<<(NPAIRS_IN + NPAIRS_EST + 255) / 256, 256>>>(input, est0);
    k_cb<<<dim3(D_ / 32, V_ / 32, F_), 256>>>(cb);
    k_nop<<<1, 32>>>();                               // pads launch order: #4 = k_sim

    for (int it = 0; it < ITERS_; it++) {
        k_sim<<<dim3(KCH, F_, 2), 256>>>(0);
        k_reduce<<<512, 256>>>();
        k_update<<<dim3(D_ / 128, F_), 256>>>();
    }
    // final similarity on converged estimates
    k_sim<<<dim3(KCH, F_, 2), 256>>>(1);
    k_reduce<<<512, 256>>>();

    float* out = (float*)d_out;
    int do_outcome = (out_size >= B_ * F_ * D_ + B_ * F_) ? 1 : 0;
    int nblk = EMIT_BLOCKS + (do_outcome ? 32 : 0);
    k_out<<<nblk, 256>>>(out, do_outcome);
}

// round 15
// speedup vs baseline: 1.0078x; 1.0078x over previous
#include <cuda_runtime.h>
#include <cuda_bf16.h>
#include <stdint.h>

#define B_ 64
#define F_ 4
#define V_ 256
#define D_ 16384
#define ITERS_ 10
#define KCH 64               // split-K chunks for stage 2 (256 CTAs -> ~2 per SM)
#define KC (D_/KCH)          // 256 k per chunk

// ---------------- static device scratch (no runtime allocation) ----------------
__device__ __align__(16) __nv_bfloat16 g_in_bf [B_*D_];                 // input, +-1 bf16
__device__ __align__(16) __nv_bfloat16 g_est_bf[B_*F_*D_];              // current estimates, +-1 bf16
__device__ __align__(16) __nv_bfloat16 g_cbK   [(size_t)F_*V_*D_];      // codebook [f][v][d] bf16
__device__ __align__(16) __nv_bfloat16 g_cbD   [(size_t)F_*D_*V_];      // codebook [f][d][v] bf16
__device__ __align__(16) float         g_simp  [(size_t)KCH*F_*B_*V_];  // split-K partials (16.7MB)
__device__ __align__(16) float         g_sim   [F_*B_*V_];              // reduced sim (exact ints)
__device__ __align__(16) __nv_bfloat16 g_Ah    [F_*B_*V_];              // sim & ~127 (exact bf16)
__device__ __align__(16) __nv_bfloat16 g_Al    [F_*B_*V_];              // sim &  127 (exact bf16)

// ---------------- mma.sync helper (bf16, fp32 accum — exact for our integer data) ----
__device__ __forceinline__ void mma16816(float c[4], const uint32_t a[4], const uint32_t b[2]) {
    asm volatile(
        "mma.sync.aligned.m16n8k16.row.col.f32.bf16.bf16.f32 "
        "{%0,%1,%2,%3},{%4,%5,%6,%7},{%8,%9},{%0,%1,%2,%3};\n"
        : "+f"(c[0]), "+f"(c[1]), "+f"(c[2]), "+f"(c[3])
        : "r"(a[0]), "r"(a[1]), "r"(a[2]), "r"(a[3]), "r"(b[0]), "r"(b[1]));
}

__device__ __forceinline__ void ldsm_x4(uint32_t& r0, uint32_t& r1, uint32_t& r2, uint32_t& r3,
                                        uint32_t saddr) {
    asm volatile("ldmatrix.sync.aligned.m8n8.x4.shared.b16 {%0,%1,%2,%3}, [%4];"
                 : "=r"(r0), "=r"(r1), "=r"(r2), "=r"(r3) : "r"(saddr));
}

// ---------------- setup: input + est signs in ONE launch ----------------
#define NPAIRS_IN  (B_*D_/2)        // 524288
#define NPAIRS_EST (B_*F_*D_/2)     // 2097152
__global__ void k_signs(const float* __restrict__ input, const float* __restrict__ est0) {
    int i = blockIdx.x * blockDim.x + threadIdx.x;
    if (i < NPAIRS_IN) {
        uint2 u = ((const uint2*)input)[i];
        ((uint32_t*)g_in_bf)[i] = 0x3F803F80u | ((u.x >> 16) & 0x8000u) | (u.y & 0x80000000u);
    } else {
        int j = i - NPAIRS_IN;
        if (j < NPAIRS_EST) {
            uint2 u = ((const uint2*)est0)[j];
            ((uint32_t*)g_est_bf)[j] = 0x3F803F80u | ((u.x >> 16) & 0x8000u) | (u.y & 0x80000000u);
        }
    }
}

// ---------------- setup: codebook -> bf16, both layouts, single fp32 read -------------
__global__ void k_cb(const float* __restrict__ cb) {
    __shared__ unsigned short ts[32][33];
    int f = blockIdx.z, d0 = blockIdx.x * 32, v0 = blockIdx.y * 32;
    int tx = threadIdx.x & 31, ty = threadIdx.x >> 5;  // 32 x 8
#pragma unroll
    for (int r = 0; r < 4; r++) {
        int v = v0 + ty + r * 8;
        uint32_t ub = __float_as_uint(cb[((size_t)(f * V_ + v)) * D_ + d0 + tx]);
        unsigned short s = (unsigned short)(0x3F80u | ((ub >> 16) & 0x8000u));
        ts[ty + r * 8][tx] = s;
        ((unsigned short*)g_cbK)[((size_t)(f * V_ + v)) * D_ + d0 + tx] = s;   // row-major
    }
    __syncthreads();
#pragma unroll
    for (int r = 0; r < 4; r++) {
        int d = d0 + ty + r * 8;
        ((unsigned short*)g_cbD)[((size_t)(f * D_ + d)) * V_ + v0 + tx] = ts[tx][ty + r * 8];
    }
}

// ---------------- nop kernel: pads launch order so ncu (-s) captures k_sim ------------
__global__ void k_nop() { }

// ---------------- stage 2: sim[f][b][v] = sum_d n * cb -------------------------------
// 512 threads / block (16 warps): each warp handles a 64(M) x 16(N) tile.
// mode 0: n = input * prod(est) * est_f inline (6-word XOR); mode 1: n = est_f.
__global__ void __launch_bounds__(512) k_sim(int mode) {
    __shared__ __align__(16) __nv_bfloat16 As[64 * 72];
    __shared__ __align__(16) __nv_bfloat16 Bs[256 * 72];
    const int kc = blockIdx.x, f = blockIdx.y;
    const int tid = threadIdx.x;
    const int w = tid >> 5, lane = tid & 31, g = lane >> 2, t = lane & 3;
    const int arow = tid >> 3, aseg = tid & 7;       // A: 64 rows x 8 uint4 segments
    const int vB = tid >> 3, chB = tid & 7;          // B: 64 rows/pass x 8 segments

    const uint4* pin = (const uint4*)(g_in_bf + (size_t)arow * D_);
    const uint4* pef = (const uint4*)(g_est_bf + ((size_t)arow * F_ + f) * D_);

    const uint32_t asBase = (uint32_t)__cvta_generic_to_shared(As);
    const uint32_t bsBase = (uint32_t)__cvta_generic_to_shared(Bs);
    const int laneRow  = lane & 15;
    const int laneColH = (lane >> 4) & 1;

    float acc[4][2][4];
#pragma unroll
    for (int mt = 0; mt < 4; mt++)
#pragma unroll
        for (int nt = 0; nt < 2; nt++)
#pragma unroll
            for (int j = 0; j < 4; j++) acc[mt][nt][j] = 0.f;

    uint4 a0;                                  // final A word (prefetched+computed)
    uint4 rB[4];                               // B prefetch regs

    // ---- A prefetch/compute for a given k-offset (one uint4 per thread) ----
    auto prefetchA = [&](int k0, uint4& o0) {
        int ai = (k0 >> 3) + aseg;             // uint4 index (8 bf16 each)
        if (mode == 0) {
            uint4 x0 = pin[ai];
            uint4 f0 = make_uint4(0, 0, 0, 0);
#pragma unroll
            for (int ff = 0; ff < F_; ff++) {
                const uint4* pe = (const uint4*)(g_est_bf + ((size_t)arow * F_ + ff) * D_);
                uint4 e0 = pe[ai];
                x0.x ^= e0.x; x0.y ^= e0.y; x0.z ^= e0.z; x0.w ^= e0.w;
                if (ff == f) f0 = e0;
            }
            // est_f appears twice (total product and unbound factor) -> xor again
            x0.x ^= f0.x; x0.y ^= f0.y; x0.z ^= f0.z; x0.w ^= f0.w;
            // 6 valid +-1 bf16 words XORed -> magnitude bits cancel; restore
            o0.x = 0x3F803F80u ^ x0.x; o0.y = 0x3F803F80u ^ x0.y;
            o0.z = 0x3F803F80u ^ x0.z; o0.w = 0x3F803F80u ^ x0.w;
        } else {
            o0 = pef[ai];
        }
    };

    // preload ks=0
    {
        const int k0 = kc * KC;
        prefetchA(k0, a0);
#pragma unroll
        for (int p = 0; p < 4; p++) {
            int v = p * 64 + vB;
            rB[p] = *(const uint4*)(g_cbK + ((size_t)(f * V_ + v)) * D_ + k0 + chB * 8);
        }
    }

    for (int ks = 0; ks < KC / 64; ks++) {
        // ---- store current tile from regs ----
        {
            *(uint4*)((uint32_t*)As + arow * 36 + aseg * 4) = a0;
#pragma unroll
            for (int p = 0; p < 4; p++)
                *(uint4*)((uint32_t*)Bs + (p * 64 + vB) * 36 + chB * 4) = rB[p];
        }
        __syncthreads();

        // ---- prefetch next tile (overlapped with mma below) ----
        if (ks + 1 < KC / 64) {
            const int k0n = kc * KC + (ks + 1) * 64;
            prefetchA(k0n, a0);
#pragma unroll
            for (int p = 0; p < 4; p++) {
                int v = p * 64 + vB;
                rB[p] = *(const uint4*)(g_cbK + ((size_t)(f * V_ + v)) * D_ + k0n + chB * 8);
            }
        }

        // ---- mma over 4 k16 steps (ldmatrix fragments; proven patterns) ----
#pragma unroll
        for (int k16 = 0; k16 < 4; k16++) {
            const int colElem = k16 * 16 + laneColH * 8;
            uint32_t a[4][4], b[2][2];
#pragma unroll
            for (int mt = 0; mt < 4; mt++) {
                uint32_t ad = asBase + ((mt * 16 + laneRow) * 72 + colElem) * 2;
                ldsm_x4(a[mt][0], a[mt][1], a[mt][2], a[mt][3], ad);
            }
            {
                uint32_t bd = bsBase + ((w * 16 + laneRow) * 72 + colElem) * 2;
                ldsm_x4(b[0][0], b[1][0], b[0][1], b[1][1], bd);
            }
#pragma unroll
            for (int mt = 0; mt < 4; mt++)
#pragma unroll
                for (int nt = 0; nt < 2; nt++) mma16816(acc[mt][nt], a[mt], b[nt]);
        }
        __syncthreads();
    }
    // --- write split-K partials ---
    float* op = g_simp + ((size_t)(kc * F_ + f) * B_) * V_;
#pragma unroll
    for (int mt = 0; mt < 4; mt++) {
        int r = mt * 16 + g;
#pragma unroll
        for (int nt = 0; nt < 2; nt++) {
            int c = w * 16 + nt * 8 + 2 * t;
            *(float2*)&op[(size_t)r * V_ + c]       = make_float2(acc[mt][nt][0], acc[mt][nt][1]);
            *(float2*)&op[(size_t)(r + 8) * V_ + c] = make_float2(acc[mt][nt][2], acc[mt][nt][3]);
        }
    }
}

// ---------------- reduce partials: 2 threads/element + shfl ----------------
__global__ void k_reduce() {
    int gid = blockIdx.x * blockDim.x + threadIdx.x;    // 131072 threads
    int i = gid >> 1;                                   // element 0..65535
    int half = gid & 1;
    float s = 0.f;
#pragma unroll
    for (int j = 0; j < KCH / 2; j++)
        s += g_simp[(size_t)(half * (KCH / 2) + j) * (F_ * B_ * V_) + i];
    s += __shfl_xor_sync(0xffffffffu, s, 1);            // pair lanes 2k / 2k+1
    if (half == 0) {
        g_sim[i] = s;
        int si = (int)s;                                // exact integer
        g_Ah[i] = __float2bfloat16((float)(si & ~127)); // multiple of 128 -> exact bf16
        g_Al[i] = __float2bfloat16((float)(si & 127));  // 0..127 -> exact bf16
    }
}

// ---------------- stage 3: est = sign( sum_v sim * cbD ) ----------------
__global__ void __launch_bounds__(256) k_update() {
    __shared__ __align__(16) __nv_bfloat16 Bs[128 * 72];
    __shared__ __align__(16) __nv_bfloat16 Ahs[64 * 72];
    __shared__ __align__(16) __nv_bfloat16 Als[64 * 72];
    const int dt = blockIdx.x, f = blockIdx.y;
    const int d0 = dt * 128;
    const int tid = threadIdx.x;
    const int w = tid >> 5, lane = tid & 31, g = lane >> 2, t = lane & 3;
    const int arow = tid >> 2, aseg = tid & 3;
    const int dB = tid >> 3, chB = tid & 7;

    const uint32_t ahBase = (uint32_t)__cvta_generic_to_shared(Ahs);
    const uint32_t alBase = (uint32_t)__cvta_generic_to_shared(Als);
    const uint32_t bsBase = (uint32_t)__cvta_generic_to_shared(Bs);
    const int laneRow  = lane & 15;
    const int laneColH = (lane >> 4) & 1;

    float acc[4][2][4];
#pragma unroll
    for (int mt = 0; mt < 4; mt++)
#pragma unroll
        for (int nt = 0; nt < 2; nt++)
#pragma unroll
            for (int j = 0; j < 4; j++) acc[mt][nt][j] = 0.f;

    uint4 h0, h1, l0, l1;
    uint4 rB[4];
    {
        const int vv = aseg * 16;
        h0 = *(const uint4*)(g_Ah + ((size_t)f * B_ + arow) * V_ + vv);
        h1 = *(const uint4*)(g_Ah + ((size_t)f * B_ + arow) * V_ + vv + 8);
        l0 = *(const uint4*)(g_Al + ((size_t)f * B_ + arow) * V_ + vv);
        l1 = *(const uint4*)(g_Al + ((size_t)f * B_ + arow) * V_ + vv + 8);
#pragma unroll
        for (int p = 0; p < 4; p++) {
            int dl = p * 32 + dB;
            rB[p] = *(const uint4*)(g_cbD + ((size_t)(f * D_ + d0 + dl)) * V_ + chB * 8);
        }
    }

    for (int vs = 0; vs < 4; vs++) {
        {
            uint4* ah = (uint4*)((uint32_t*)Ahs + arow * 36 + aseg * 8);
            uint4* al = (uint4*)((uint32_t*)Als + arow * 36 + aseg * 8);
            ah[0] = h0; ah[1] = h1;
            al[0] = l0; al[1] = l1;
#pragma unroll
            for (int p = 0; p < 4; p++)
                *(uint4*)((uint32_t*)Bs + (p * 32 + dB) * 36 + chB * 4) = rB[p];
        }
        __syncthreads();

        if (vs + 1 < 4) {
            const int v0n = (vs + 1) * 64;
            const int vv = v0n + aseg * 16;
            h0 = *(const uint4*)(g_Ah + ((size_t)f * B_ + arow) * V_ + vv);
            h1 = *(const uint4*)(g_Ah + ((size_t)f * B_ + arow) * V_ + vv + 8);
            l0 = *(const uint4*)(g_Al + ((size_t)f * B_ + arow) * V_ + vv);
            l1 = *(const uint4*)(g_Al + ((size_t)f * B_ + arow) * V_ + vv + 8);
#pragma unroll
            for (int p = 0; p < 4; p++) {
                int dl = p * 32 + dB;
                rB[p] = *(const uint4*)(g_cbD + ((size_t)(f * D_ + d0 + dl)) * V_ + v0n + chB * 8);
            }
        }

#pragma unroll
        for (int k16 = 0; k16 < 4; k16++) {
            const int colElem = k16 * 16 + laneColH * 8;
            uint32_t fa[4][4], fl[4][4], b[2][2];
#pragma unroll
            for (int mt = 0; mt < 4; mt++) {
                uint32_t adh = ahBase + ((mt * 16 + laneRow) * 72 + colElem) * 2;
                uint32_t adl = alBase + ((mt * 16 + laneRow) * 72 + colElem) * 2;
                ldsm_x4(fa[mt][0], fa[mt][1], fa[mt][2], fa[mt][3], adh);
                ldsm_x4(fl[mt][0], fl[mt][1], fl[mt][2], fl[mt][3], adl);
            }
            {
                uint32_t bd = bsBase + ((w * 16 + laneRow) * 72 + colElem) * 2;
                ldsm_x4(b[0][0], b[1][0], b[0][1], b[1][1], bd);
            }
#pragma unroll
            for (int mt = 0; mt < 4; mt++)
#pragma unroll
                for (int nt = 0; nt < 2; nt++) {
                    mma16816(acc[mt][nt], fa[mt], b[nt]);
                    mma16816(acc[mt][nt], fl[mt], b[nt]);
                }
        }
        __syncthreads();
    }
#pragma unroll
    for (int mt = 0; mt < 4; mt++) {
        int r = mt * 16 + g;
#pragma unroll
        for (int nt = 0; nt < 2; nt++) {
            int d = d0 + w * 16 + nt * 8 + 2 * t;
            uint32_t s0 = __float_as_uint(acc[mt][nt][0]);
            uint32_t s1 = __float_as_uint(acc[mt][nt][1]);
            uint32_t s2 = __float_as_uint(acc[mt][nt][2]);
            uint32_t s3 = __float_as_uint(acc[mt][nt][3]);
            uint32_t w0 = 0x3F803F80u | ((s0 >> 16) & 0x8000u) | (s1 & 0x80000000u);
            uint32_t w1 = 0x3F803F80u | ((s2 >> 16) & 0x8000u) | (s3 & 0x80000000u);
            ((uint32_t*)g_est_bf)[(((size_t)r * F_ + f) * D_ + d) >> 1] = w0;
            ((uint32_t*)g_est_bf)[(((size_t)(r + 8) * F_ + f) * D_ + d) >> 1] = w1;
        }
    }
}

// ---------------- outputs: est emit + outcome in ONE launch ----------------
#define EMIT_BLOCKS ((B_*F_*D_/2 + 255) / 256)     // 8192
__global__ void k_out(float* __restrict__ out, int do_outcome) {
    int blk = blockIdx.x;
    if (blk < EMIT_BLOCKS) {
        int i = blk * 256 + threadIdx.x;
        if (i < B_ * F_ * D_ / 2) {
            uint32_t w = ((const uint32_t*)g_est_bf)[i];
            float2 o;
            o.x = (w & 0x8000u) ? -1.f : 1.f;
            o.y = (w & 0x80000000u) ? -1.f : 1.f;
            ((float2*)out)[i] = o;
        }
    } else if (do_outcome) {
        int warp = (blk - EMIT_BLOCKS) * 8 + (threadIdx.x >> 5);
        int lane = threadIdx.x & 31;
        if (warp >= B_ * F_) return;
        int b = warp >> 2, f = warp & 3;
        const float* s = g_sim + ((size_t)(f * B_ + b)) * V_;
        float best = -1.f; int bi = 0;
#pragma unroll
        for (int j = 0; j < 8; j++) {
            int v = j * 32 + lane;
            float a = fabsf(s[v]);
            if (a > best) { best = a; bi = v; }
        }
#pragma unroll
        for (int off = 16; off; off >>= 1) {
            float ob = __shfl_down_sync(0xffffffffu, best, off);
            int   oi = __shfl_down_sync(0xffffffffu, bi, off);
            if (ob > best || (ob == best && oi < bi)) { best = ob; bi = oi; }
        }
        if (lane == 0) out[(size_t)B_ * F_ * D_ + warp] = (float)bi;
    }
}

// ---------------- host launch ----------------
extern "C" void kernel_launch(void* const* d_in, const int* in_sizes, int n_in,
                              void* d_out, int out_size) {
    const float *input = nullptr, *est0 = nullptr, *cb = nullptr;
    for (int i = 0; i < n_in; i++) {
        if      (in_sizes[i] == B_ * D_)        input = (const float*)d_in[i];
        else if (in_sizes[i] == B_ * F_ * D_)   est0  = (const float*)d_in[i];
        else if (in_sizes[i] == F_ * V_ * D_)   cb    = (const float*)d_in[i];
    }
    if (!input && n_in > 0) input = (const float*)d_in[0];
    if (!est0  && n_in > 1) est0  = (const float*)d_in[1];
    if (!cb    && n_in > 2) cb    = (const float*)d_in[2];

    k_signs<<<(NPAIRS_IN + NPAIRS_EST + 255) / 256, 256>>>(input, est0);
    k_cb<<<dim3(D_ / 32, V_ / 32, F_), 256>>>(cb);
    k_nop<<<1, 32>>>();                               // pads launch order: #4 = k_sim

    for (int it = 0; it < ITERS_; it++) {
        k_sim<<<dim3(KCH, F_), 512>>>(0);
        k_reduce<<<512, 256>>>();
        k_update<<<dim3(D_ / 128, F_), 256>>>();
    }
    // final similarity on converged estimates
    k_sim<<<dim3(KCH, F_), 512>>>(1);
    k_reduce<<<512, 256>>>();

    float* out = (float*)d_out;
    int do_outcome = (out_size >= B_ * F_ * D_ + B_ * F_) ? 1 : 0;
    int nblk = EMIT_BLOCKS + (do_outcome ? 32 : 0);
    k_out<<<nblk, 256>>>(out, do_outcome);
}

// round 16
// speedup vs baseline: 1.0665x; 1.0582x over previous
#include <cuda_runtime.h>
#include <cuda_bf16.h>
#include <stdint.h>

#define B_ 64
#define F_ 4
#define V_ 256
#define D_ 16384
#define ITERS_ 10
#define KCH 64               // split-K chunks (256 CTAs; K-split adds NO redundant traffic)
#define KC (D_/KCH)          // 256 k per chunk

// ---------------- static device scratch (no runtime allocation) ----------------
__device__ __align__(16) __nv_bfloat16 g_in_bf [B_*D_];                 // input, +-1 bf16
__device__ __align__(16) __nv_bfloat16 g_est_bf[B_*F_*D_];              // current estimates, +-1 bf16
__device__ __align__(16) __nv_bfloat16 g_cbK   [(size_t)F_*V_*D_];      // codebook [f][v][d] bf16
__device__ __align__(16) __nv_bfloat16 g_cbD   [(size_t)F_*D_*V_];      // codebook [f][d][v] bf16
__device__ __align__(16) float         g_simp  [(size_t)KCH*F_*B_*V_];  // split-K partials (16.7MB)
__device__ __align__(16) float         g_sim   [F_*B_*V_];              // reduced sim (exact ints)
__device__ __align__(16) __nv_bfloat16 g_Ah    [F_*B_*V_];              // sim & ~127 (exact bf16)
__device__ __align__(16) __nv_bfloat16 g_Al    [F_*B_*V_];              // sim &  127 (exact bf16)

// ---------------- mma.sync helper (bf16, fp32 accum — exact for our integer data) ----
__device__ __forceinline__ void mma16816(float c[4], const uint32_t a[4], const uint32_t b[2]) {
    asm volatile(
        "mma.sync.aligned.m16n8k16.row.col.f32.bf16.bf16.f32 "
        "{%0,%1,%2,%3},{%4,%5,%6,%7},{%8,%9},{%0,%1,%2,%3};\n"
        : "+f"(c[0]), "+f"(c[1]), "+f"(c[2]), "+f"(c[3])
        : "r"(a[0]), "r"(a[1]), "r"(a[2]), "r"(a[3]), "r"(b[0]), "r"(b[1]));
}

__device__ __forceinline__ void ldsm_x4(uint32_t& r0, uint32_t& r1, uint32_t& r2, uint32_t& r3,
                                        uint32_t saddr) {
    asm volatile("ldmatrix.sync.aligned.m8n8.x4.shared.b16 {%0,%1,%2,%3}, [%4];"
                 : "=r"(r0), "=r"(r1), "=r"(r2), "=r"(r3) : "r"(saddr));
}

// ---------------- setup: input + est signs in ONE launch ----------------
#define NPAIRS_IN  (B_*D_/2)        // 524288
#define NPAIRS_EST (B_*F_*D_/2)     // 2097152
__global__ void k_signs(const float* __restrict__ input, const float* __restrict__ est0) {
    int i = blockIdx.x * blockDim.x + threadIdx.x;
    if (i < NPAIRS_IN) {
        uint2 u = ((const uint2*)input)[i];
        ((uint32_t*)g_in_bf)[i] = 0x3F803F80u | ((u.x >> 16) & 0x8000u) | (u.y & 0x80000000u);
    } else {
        int j = i - NPAIRS_IN;
        if (j < NPAIRS_EST) {
            uint2 u = ((const uint2*)est0)[j];
            ((uint32_t*)g_est_bf)[j] = 0x3F803F80u | ((u.x >> 16) & 0x8000u) | (u.y & 0x80000000u);
        }
    }
}

// ---------------- setup: codebook -> bf16, both layouts, single fp32 read -------------
__global__ void k_cb(const float* __restrict__ cb) {
    __shared__ unsigned short ts[32][33];
    int f = blockIdx.z, d0 = blockIdx.x * 32, v0 = blockIdx.y * 32;
    int tx = threadIdx.x & 31, ty = threadIdx.x >> 5;  // 32 x 8
#pragma unroll
    for (int r = 0; r < 4; r++) {
        int v = v0 + ty + r * 8;
        uint32_t ub = __float_as_uint(cb[((size_t)(f * V_ + v)) * D_ + d0 + tx]);
        unsigned short s = (unsigned short)(0x3F80u | ((ub >> 16) & 0x8000u));
        ts[ty + r * 8][tx] = s;
        ((unsigned short*)g_cbK)[((size_t)(f * V_ + v)) * D_ + d0 + tx] = s;   // row-major
    }
    __syncthreads();
#pragma unroll
    for (int r = 0; r < 4; r++) {
        int d = d0 + ty + r * 8;
        ((unsigned short*)g_cbD)[((size_t)(f * D_ + d)) * V_ + v0 + tx] = ts[tx][ty + r * 8];
    }
}

// ---------------- nop kernel: pads launch order so ncu (-s) captures k_sim ------------
__global__ void k_nop() { }

// ---------------- stage 2: sim[f][b][v] = sum_d n * cb -------------------------------
// 256 threads (8 warps, nt=4 — HW-proven R7/R10 body), KCH=64 -> 256 CTAs.
// __launch_bounds__(256,2) caps regs at 128 so 2 CTAs truly co-reside per SM.
// mode 0: n = input * prod(est) * est_f inline (6-word XOR); mode 1: n = est_f.
__global__ void __launch_bounds__(256, 2) k_sim(int mode) {
    __shared__ __align__(16) __nv_bfloat16 As[64 * 72];
    __shared__ __align__(16) __nv_bfloat16 Bs[256 * 72];
    const int kc = blockIdx.x, f = blockIdx.y;
    const int tid = threadIdx.x;
    const int w = tid >> 5, lane = tid & 31, g = lane >> 2, t = lane & 3;
    const int arow = tid >> 2, aseg = tid & 3;       // A: 64 rows x 4 seg-pairs (2 uint4 each)
    const int vB = tid >> 3, chB = tid & 7;          // B: 32 rows/pass x 8 segments

    const uint4* pin = (const uint4*)(g_in_bf + (size_t)arow * D_);
    const uint4* pef = (const uint4*)(g_est_bf + ((size_t)arow * F_ + f) * D_);

    const uint32_t asBase = (uint32_t)__cvta_generic_to_shared(As);
    const uint32_t bsBase = (uint32_t)__cvta_generic_to_shared(Bs);
    const int laneRow  = lane & 15;
    const int laneColH = (lane >> 4) & 1;

    float acc[4][4][4];
#pragma unroll
    for (int mt = 0; mt < 4; mt++)
#pragma unroll
        for (int nt = 0; nt < 4; nt++)
#pragma unroll
            for (int j = 0; j < 4; j++) acc[mt][nt][j] = 0.f;

    uint4 a0, a1;                              // final A words (prefetched+computed)
    uint4 rB[8];                               // B prefetch regs

    // ---- A fetch/compute of ONE uint4 at uint4-index ai (R7-proven 6-word XOR) ----
    auto fetchA = [&](int ai) -> uint4 {
        if (mode == 0) {
            uint4 x0 = pin[ai];
            uint4 f0 = make_uint4(0, 0, 0, 0);
#pragma unroll
            for (int ff = 0; ff < F_; ff++) {
                const uint4* pe = (const uint4*)(g_est_bf + ((size_t)arow * F_ + ff) * D_);
                uint4 e0 = pe[ai];
                x0.x ^= e0.x; x0.y ^= e0.y; x0.z ^= e0.z; x0.w ^= e0.w;
                if (ff == f) f0 = e0;
            }
            // est_f appears twice (total product and unbound factor) -> xor again
            x0.x ^= f0.x; x0.y ^= f0.y; x0.z ^= f0.z; x0.w ^= f0.w;
            // 6 valid +-1 bf16 words XORed -> magnitude bits cancel; restore
            uint4 o;
            o.x = 0x3F803F80u ^ x0.x; o.y = 0x3F803F80u ^ x0.y;
            o.z = 0x3F803F80u ^ x0.z; o.w = 0x3F803F80u ^ x0.w;
            return o;
        } else {
            return pef[ai];
        }
    };

    // preload ks=0
    {
        const int k0 = kc * KC;
        const int ai0 = (k0 >> 3) + aseg * 2;
        a0 = fetchA(ai0); a1 = fetchA(ai0 + 1);
#pragma unroll
        for (int p = 0; p < 8; p++) {
            int v = p * 32 + vB;
            rB[p] = *(const uint4*)(g_cbK + ((size_t)(f * V_ + v)) * D_ + k0 + chB * 8);
        }
    }

    for (int ks = 0; ks < KC / 64; ks++) {      // 4 iterations
        // ---- store current tile from regs ----
        {
            uint4* as = (uint4*)((uint32_t*)As + arow * 36 + aseg * 8);
            as[0] = a0; as[1] = a1;
#pragma unroll
            for (int p = 0; p < 8; p++)
                *(uint4*)((uint32_t*)Bs + (p * 32 + vB) * 36 + chB * 4) = rB[p];
        }
        __syncthreads();

        // ---- prefetch next tile (overlapped with mma below) ----
        if (ks + 1 < KC / 64) {
            const int k0n = kc * KC + (ks + 1) * 64;
            const int ai0 = (k0n >> 3) + aseg * 2;
            a0 = fetchA(ai0); a1 = fetchA(ai0 + 1);
#pragma unroll
            for (int p = 0; p < 8; p++) {
                int v = p * 32 + vB;
                rB[p] = *(const uint4*)(g_cbK + ((size_t)(f * V_ + v)) * D_ + k0n + chB * 8);
            }
        }

        // ---- mma over 4 k16 steps (ldmatrix fragments; R7-proven) ----
#pragma unroll
        for (int k16 = 0; k16 < 4; k16++) {
            const int colElem = k16 * 16 + laneColH * 8;
            uint32_t a[4][4], b[4][2];
#pragma unroll
            for (int mt = 0; mt < 4; mt++) {
                uint32_t ad = asBase + ((mt * 16 + laneRow) * 72 + colElem) * 2;
                ldsm_x4(a[mt][0], a[mt][1], a[mt][2], a[mt][3], ad);
            }
#pragma unroll
            for (int h = 0; h < 2; h++) {
                uint32_t bd = bsBase + ((w * 32 + h * 16 + laneRow) * 72 + colElem) * 2;
                ldsm_x4(b[2 * h][0], b[2 * h + 1][0], b[2 * h][1], b[2 * h + 1][1], bd);
            }
#pragma unroll
            for (int mt = 0; mt < 4; mt++)
#pragma unroll
                for (int nt = 0; nt < 4; nt++) mma16816(acc[mt][nt], a[mt], b[nt]);
        }
        __syncthreads();
    }
    // --- write split-K partials ---
    float* op = g_simp + ((size_t)(kc * F_ + f) * B_) * V_;
#pragma unroll
    for (int mt = 0; mt < 4; mt++) {
        int r = mt * 16 + g;
#pragma unroll
        for (int nt = 0; nt < 4; nt++) {
            int c = w * 32 + nt * 8 + 2 * t;
            *(float2*)&op[(size_t)r * V_ + c]       = make_float2(acc[mt][nt][0], acc[mt][nt][1]);
            *(float2*)&op[(size_t)(r + 8) * V_ + c] = make_float2(acc[mt][nt][2], acc[mt][nt][3]);
        }
    }
}

// ---------------- reduce partials: 2 threads/element + shfl ----------------
__global__ void k_reduce() {
    int gid = blockIdx.x * blockDim.x + threadIdx.x;    // 131072 threads
    int i = gid >> 1;                                   // element 0..65535
    int half = gid & 1;
    float s = 0.f;
#pragma unroll
    for (int j = 0; j < KCH / 2; j++)
        s += g_simp[(size_t)(half * (KCH / 2) + j) * (F_ * B_ * V_) + i];
    s += __shfl_xor_sync(0xffffffffu, s, 1);            // pair lanes 2k / 2k+1
    if (half == 0) {
        g_sim[i] = s;
        int si = (int)s;                                // exact integer
        g_Ah[i] = __float2bfloat16((float)(si & ~127)); // multiple of 128 -> exact bf16
        g_Al[i] = __float2bfloat16((float)(si & 127));  // 0..127 -> exact bf16
    }
}

// ---------------- stage 3: est = sign( sum_v sim * cbD ) ----------------
__global__ void __launch_bounds__(256) k_update() {
    __shared__ __align__(16) __nv_bfloat16 Bs[128 * 72];
    __shared__ __align__(16) __nv_bfloat16 Ahs[64 * 72];
    __shared__ __align__(16) __nv_bfloat16 Als[64 * 72];
    const int dt = blockIdx.x, f = blockIdx.y;
    const int d0 = dt * 128;
    const int tid = threadIdx.x;
    const int w = tid >> 5, lane = tid & 31, g = lane >> 2, t = lane & 3;
    const int arow = tid >> 2, aseg = tid & 3;
    const int dB = tid >> 3, chB = tid & 7;

    const uint32_t ahBase = (uint32_t)__cvta_generic_to_shared(Ahs);
    const uint32_t alBase = (uint32_t)__cvta_generic_to_shared(Als);
    const uint32_t bsBase = (uint32_t)__cvta_generic_to_shared(Bs);
    const int laneRow  = lane & 15;
    const int laneColH = (lane >> 4) & 1;

    float acc[4][2][4];
#pragma unroll
    for (int mt = 0; mt < 4; mt++)
#pragma unroll
        for (int nt = 0; nt < 2; nt++)
#pragma unroll
            for (int j = 0; j < 4; j++) acc[mt][nt][j] = 0.f;

    uint4 h0, h1, l0, l1;
    uint4 rB[4];
    {
        const int vv = aseg * 16;
        h0 = *(const uint4*)(g_Ah + ((size_t)f * B_ + arow) * V_ + vv);
        h1 = *(const uint4*)(g_Ah + ((size_t)f * B_ + arow) * V_ + vv + 8);
        l0 = *(const uint4*)(g_Al + ((size_t)f * B_ + arow) * V_ + vv);
        l1 = *(const uint4*)(g_Al + ((size_t)f * B_ + arow) * V_ + vv + 8);
#pragma unroll
        for (int p = 0; p < 4; p++) {
            int dl = p * 32 + dB;
            rB[p] = *(const uint4*)(g_cbD + ((size_t)(f * D_ + d0 + dl)) * V_ + chB * 8);
        }
    }

    for (int vs = 0; vs < 4; vs++) {
        {
            uint4* ah = (uint4*)((uint32_t*)Ahs + arow * 36 + aseg * 8);
            uint4* al = (uint4*)((uint32_t*)Als + arow * 36 + aseg * 8);
            ah[0] = h0; ah[1] = h1;
            al[0] = l0; al[1] = l1;
#pragma unroll
            for (int p = 0; p < 4; p++)
                *(uint4*)((uint32_t*)Bs + (p * 32 + dB) * 36 + chB * 4) = rB[p];
        }
        __syncthreads();

        if (vs + 1 < 4) {
            const int v0n = (vs + 1) * 64;
            const int vv = v0n + aseg * 16;
            h0 = *(const uint4*)(g_Ah + ((size_t)f * B_ + arow) * V_ + vv);
            h1 = *(const uint4*)(g_Ah + ((size_t)f * B_ + arow) * V_ + vv + 8);
            l0 = *(const uint4*)(g_Al + ((size_t)f * B_ + arow) * V_ + vv);
            l1 = *(const uint4*)(g_Al + ((size_t)f * B_ + arow) * V_ + vv + 8);
#pragma unroll
            for (int p = 0; p < 4; p++) {
                int dl = p * 32 + dB;
                rB[p] = *(const uint4*)(g_cbD + ((size_t)(f * D_ + d0 + dl)) * V_ + v0n + chB * 8);
            }
        }

#pragma unroll
        for (int k16 = 0; k16 < 4; k16++) {
            const int colElem = k16 * 16 + laneColH * 8;
            uint32_t fa[4][4], fl[4][4], b[2][2];
#pragma unroll
            for (int mt = 0; mt < 4; mt++) {
                uint32_t adh = ahBase + ((mt * 16 + laneRow) * 72 + colElem) * 2;
                uint32_t adl = alBase + ((mt * 16 + laneRow) * 72 + colElem) * 2;
                ldsm_x4(fa[mt][0], fa[mt][1], fa[mt][2], fa[mt][3], adh);
                ldsm_x4(fl[mt][0], fl[mt][1], fl[mt][2], fl[mt][3], adl);
            }
            {
                uint32_t bd = bsBase + ((w * 16 + laneRow) * 72 + colElem) * 2;
                ldsm_x4(b[0][0], b[1][0], b[0][1], b[1][1], bd);
            }
#pragma unroll
            for (int mt = 0; mt < 4; mt++)
#pragma unroll
                for (int nt = 0; nt < 2; nt++) {
                    mma16816(acc[mt][nt], fa[mt], b[nt]);
                    mma16816(acc[mt][nt], fl[mt], b[nt]);
                }
        }
        __syncthreads();
    }
#pragma unroll
    for (int mt = 0; mt < 4; mt++) {
        int r = mt * 16 + g;
#pragma unroll
        for (int nt = 0; nt < 2; nt++) {
            int d = d0 + w * 16 + nt * 8 + 2 * t;
            uint32_t s0 = __float_as_uint(acc[mt][nt][0]);
            uint32_t s1 = __float_as_uint(acc[mt][nt][1]);
            uint32_t s2 = __float_as_uint(acc[mt][nt][2]);
            uint32_t s3 = __float_as_uint(acc[mt][nt][3]);
            uint32_t w0 = 0x3F803F80u | ((s0 >> 16) & 0x8000u) | (s1 & 0x80000000u);
            uint32_t w1 = 0x3F803F80u | ((s2 >> 16) & 0x8000u) | (s3 & 0x80000000u);
            ((uint32_t*)g_est_bf)[(((size_t)r * F_ + f) * D_ + d) >> 1] = w0;
            ((uint32_t*)g_est_bf)[(((size_t)(r + 8) * F_ + f) * D_ + d) >> 1] = w1;
        }
    }
}

// ---------------- outputs: est emit + outcome in ONE launch ----------------
#define EMIT_BLOCKS ((B_*F_*D_/2 + 255) / 256)     // 8192
__global__ void k_out(float* __restrict__ out, int do_outcome) {
    int blk = blockIdx.x;
    if (blk < EMIT_BLOCKS) {
        int i = blk * 256 + threadIdx.x;
        if (i < B_ * F_ * D_ / 2) {
            uint32_t w = ((const uint32_t*)g_est_bf)[i];
            float2 o;
            o.x = (w & 0x8000u) ? -1.f : 1.f;
            o.y = (w & 0x80000000u) ? -1.f : 1.f;
            ((float2*)out)[i] = o;
        }
    } else if (do_outcome) {
        int warp = (blk - EMIT_BLOCKS) * 8 + (threadIdx.x >> 5);
        int lane = threadIdx.x & 31;
        if (warp >= B_ * F_) return;
        int b = warp >> 2, f = warp & 3;
        const float* s = g_sim + ((size_t)(f * B_ + b)) * V_;
        float best = -1.f; int bi = 0;
#pragma unroll
        for (int j = 0; j < 8; j++) {
            int v = j * 32 + lane;
            float a = fabsf(s[v]);
            if (a > best) { best = a; bi = v; }
        }
#pragma unroll
        for (int off = 16; off; off >>= 1) {
            float ob = __shfl_down_sync(0xffffffffu, best, off);
            int   oi = __shfl_down_sync(0xffffffffu, bi, off);
            if (ob > best || (ob == best && oi < bi)) { best = ob; bi = oi; }
        }
        if (lane == 0) out[(size_t)B_ * F_ * D_ + warp] = (float)bi;
    }
}

// ---------------- host launch ----------------
extern "C" void kernel_launch(void* const* d_in, const int* in_sizes, int n_in,
                              void* d_out, int out_size) {
    const float *input = nullptr, *est0 = nullptr, *cb = nullptr;
    for (int i = 0; i < n_in; i++) {
        if      (in_sizes[i] == B_ * D_)        input = (const float*)d_in[i];
        else if (in_sizes[i] == B_ * F_ * D_)   est0  = (const float*)d_in[i];
        else if (in_sizes[i] == F_ * V_ * D_)   cb    = (const float*)d_in[i];
    }
    if (!input && n_in > 0) input = (const float*)d_in[0];
    if (!est0  && n_in > 1) est0  = (const float*)d_in[1];
    if (!cb    && n_in > 2) cb    = (const float*)d_in[2];

    k_signs<<<(NPAIRS_IN + NPAIRS_EST + 255) / 256, 256>>>(input, est0);
    k_cb<<<dim3(D_ / 32, V_ / 32, F_), 256>>>(cb);
    k_nop<<<1, 32>>>();                               // pads launch order: #4 = k_sim

    for (int it = 0; it < ITERS_; it++) {
        k_sim<<<dim3(KCH, F_), 256>>>(0);
        k_reduce<<<512, 256>>>();
        k_update<<<dim3(D_ / 128, F_), 256>>>();
    }
    // final similarity on converged estimates
    k_sim<<<dim3(KCH, F_), 256>>>(1);
    k_reduce<<<512, 256>>>();

    float* out = (float*)d_out;
    int do_outcome = (out_size >= B_ * F_ * D_ + B_ * F_) ? 1 : 0;
    int nblk = EMIT_BLOCKS + (do_outcome ? 32 : 0);
    k_out<<<nblk, 256>>>(out, do_outcome);
}

// round 17
// speedup vs baseline: 1.0707x; 1.0040x over previous
#include <cuda_runtime.h>
#include <cuda_bf16.h>
#include <stdint.h>

#define B_ 64
#define F_ 4
#define V_ 256
#define D_ 16384
#define ITERS_ 10
#define KCH 64               // split-K chunks (256 CTAs; K-split adds NO redundant traffic)
#define KC (D_/KCH)          // 256 k per chunk -> each partial in [-256,256], exact int16

// ---------------- static device scratch (no runtime allocation) ----------------
__device__ __align__(16) __nv_bfloat16 g_in_bf [B_*D_];                 // input, +-1 bf16
__device__ __align__(16) __nv_bfloat16 g_est_bf[B_*F_*D_];              // current estimates, +-1 bf16
__device__ __align__(16) __nv_bfloat16 g_cbK   [(size_t)F_*V_*D_];      // codebook [f][v][d] bf16
__device__ __align__(16) __nv_bfloat16 g_cbD   [(size_t)F_*D_*V_];      // codebook [f][d][v] bf16
__device__ __align__(16) short         g_simp  [(size_t)KCH*F_*B_*V_];  // split-K partials (8.3MB, int16)
__device__ __align__(16) float         g_sim   [F_*B_*V_];              // reduced sim (exact ints)
__device__ __align__(16) __nv_bfloat16 g_Ah    [F_*B_*V_];              // sim & ~127 (exact bf16)
__device__ __align__(16) __nv_bfloat16 g_Al    [F_*B_*V_];              // sim &  127 (exact bf16)

// ---------------- mma.sync helper (bf16, fp32 accum — exact for our integer data) ----
__device__ __forceinline__ void mma16816(float c[4], const uint32_t a[4], const uint32_t b[2]) {
    asm volatile(
        "mma.sync.aligned.m16n8k16.row.col.f32.bf16.bf16.f32 "
        "{%0,%1,%2,%3},{%4,%5,%6,%7},{%8,%9},{%0,%1,%2,%3};\n"
        : "+f"(c[0]), "+f"(c[1]), "+f"(c[2]), "+f"(c[3])
        : "r"(a[0]), "r"(a[1]), "r"(a[2]), "r"(a[3]), "r"(b[0]), "r"(b[1]));
}

__device__ __forceinline__ void ldsm_x4(uint32_t& r0, uint32_t& r1, uint32_t& r2, uint32_t& r3,
                                        uint32_t saddr) {
    asm volatile("ldmatrix.sync.aligned.m8n8.x4.shared.b16 {%0,%1,%2,%3}, [%4];"
                 : "=r"(r0), "=r"(r1), "=r"(r2), "=r"(r3) : "r"(saddr));
}

// ---------------- setup: input + est signs in ONE launch ----------------
#define NPAIRS_IN  (B_*D_/2)        // 524288
#define NPAIRS_EST (B_*F_*D_/2)     // 2097152
__global__ void k_signs(const float* __restrict__ input, const float* __restrict__ est0) {
    int i = blockIdx.x * blockDim.x + threadIdx.x;
    if (i < NPAIRS_IN) {
        uint2 u = ((const uint2*)input)[i];
        ((uint32_t*)g_in_bf)[i] = 0x3F803F80u | ((u.x >> 16) & 0x8000u) | (u.y & 0x80000000u);
    } else {
        int j = i - NPAIRS_IN;
        if (j < NPAIRS_EST) {
            uint2 u = ((const uint2*)est0)[j];
            ((uint32_t*)g_est_bf)[j] = 0x3F803F80u | ((u.x >> 16) & 0x8000u) | (u.y & 0x80000000u);
        }
    }
}

// ---------------- setup: codebook -> bf16, both layouts, single fp32 read -------------
__global__ void k_cb(const float* __restrict__ cb) {
    __shared__ unsigned short ts[32][33];
    int f = blockIdx.z, d0 = blockIdx.x * 32, v0 = blockIdx.y * 32;
    int tx = threadIdx.x & 31, ty = threadIdx.x >> 5;  // 32 x 8
#pragma unroll
    for (int r = 0; r < 4; r++) {
        int v = v0 + ty + r * 8;
        uint32_t ub = __float_as_uint(cb[((size_t)(f * V_ + v)) * D_ + d0 + tx]);
        unsigned short s = (unsigned short)(0x3F80u | ((ub >> 16) & 0x8000u));
        ts[ty + r * 8][tx] = s;
        ((unsigned short*)g_cbK)[((size_t)(f * V_ + v)) * D_ + d0 + tx] = s;   // row-major
    }
    __syncthreads();
#pragma unroll
    for (int r = 0; r < 4; r++) {
        int d = d0 + ty + r * 8;
        ((unsigned short*)g_cbD)[((size_t)(f * D_ + d)) * V_ + v0 + tx] = ts[tx][ty + r * 8];
    }
}

// ---------------- nop kernel: pads launch order so ncu (-s) captures k_sim ------------
__global__ void k_nop() { }

// ---------------- stage 2: sim[f][b][v] = sum_d n * cb -------------------------------
// 256 threads (8 warps, nt=4 — HW-proven body), KCH=64 -> 256 CTAs, 2 co-resident/SM.
// mode 0: n = input * prod(est) * est_f inline (6-word XOR); mode 1: n = est_f.
__global__ void __launch_bounds__(256, 2) k_sim(int mode) {
    __shared__ __align__(16) __nv_bfloat16 As[64 * 72];
    __shared__ __align__(16) __nv_bfloat16 Bs[256 * 72];
    const int kc = blockIdx.x, f = blockIdx.y;
    const int tid = threadIdx.x;
    const int w = tid >> 5, lane = tid & 31, g = lane >> 2, t = lane & 3;
    const int arow = tid >> 2, aseg = tid & 3;       // A: 64 rows x 4 seg-pairs (2 uint4 each)
    const int vB = tid >> 3, chB = tid & 7;          // B: 32 rows/pass x 8 segments

    const uint4* pin = (const uint4*)(g_in_bf + (size_t)arow * D_);
    const uint4* pef = (const uint4*)(g_est_bf + ((size_t)arow * F_ + f) * D_);

    const uint32_t asBase = (uint32_t)__cvta_generic_to_shared(As);
    const uint32_t bsBase = (uint32_t)__cvta_generic_to_shared(Bs);
    const int laneRow  = lane & 15;
    const int laneColH = (lane >> 4) & 1;

    float acc[4][4][4];
#pragma unroll
    for (int mt = 0; mt < 4; mt++)
#pragma unroll
        for (int nt = 0; nt < 4; nt++)
#pragma unroll
            for (int j = 0; j < 4; j++) acc[mt][nt][j] = 0.f;

    uint4 a0, a1;                              // final A words (prefetched+computed)
    uint4 rB[8];                               // B prefetch regs

    // ---- A fetch/compute of ONE uint4 at uint4-index ai (proven 6-word XOR) ----
    auto fetchA = [&](int ai) -> uint4 {
        if (mode == 0) {
            uint4 x0 = pin[ai];
            uint4 f0 = make_uint4(0, 0, 0, 0);
#pragma unroll
            for (int ff = 0; ff < F_; ff++) {
                const uint4* pe = (const uint4*)(g_est_bf + ((size_t)arow * F_ + ff) * D_);
                uint4 e0 = pe[ai];
                x0.x ^= e0.x; x0.y ^= e0.y; x0.z ^= e0.z; x0.w ^= e0.w;
                if (ff == f) f0 = e0;
            }
            // est_f appears twice (total product and unbound factor) -> xor again
            x0.x ^= f0.x; x0.y ^= f0.y; x0.z ^= f0.z; x0.w ^= f0.w;
            // 6 valid +-1 bf16 words XORed -> magnitude bits cancel; restore
            uint4 o;
            o.x = 0x3F803F80u ^ x0.x; o.y = 0x3F803F80u ^ x0.y;
            o.z = 0x3F803F80u ^ x0.z; o.w = 0x3F803F80u ^ x0.w;
            return o;
        } else {
            return pef[ai];
        }
    };

    // preload ks=0
    {
        const int k0 = kc * KC;
        const int ai0 = (k0 >> 3) + aseg * 2;
        a0 = fetchA(ai0); a1 = fetchA(ai0 + 1);
#pragma unroll
        for (int p = 0; p < 8; p++) {
            int v = p * 32 + vB;
            rB[p] = *(const uint4*)(g_cbK + ((size_t)(f * V_ + v)) * D_ + k0 + chB * 8);
        }
    }

    for (int ks = 0; ks < KC / 64; ks++) {      // 4 iterations
        // ---- store current tile from regs ----
        {
            uint4* as = (uint4*)((uint32_t*)As + arow * 36 + aseg * 8);
            as[0] = a0; as[1] = a1;
#pragma unroll
            for (int p = 0; p < 8; p++)
                *(uint4*)((uint32_t*)Bs + (p * 32 + vB) * 36 + chB * 4) = rB[p];
        }
        __syncthreads();

        // ---- prefetch next tile (overlapped with mma below) ----
        if (ks + 1 < KC / 64) {
            const int k0n = kc * KC + (ks + 1) * 64;
            const int ai0 = (k0n >> 3) + aseg * 2;
            a0 = fetchA(ai0); a1 = fetchA(ai0 + 1);
#pragma unroll
            for (int p = 0; p < 8; p++) {
                int v = p * 32 + vB;
                rB[p] = *(const uint4*)(g_cbK + ((size_t)(f * V_ + v)) * D_ + k0n + chB * 8);
            }
        }

        // ---- mma over 4 k16 steps (ldmatrix fragments; proven) ----
#pragma unroll
        for (int k16 = 0; k16 < 4; k16++) {
            const int colElem = k16 * 16 + laneColH * 8;
            uint32_t a[4][4], b[4][2];
#pragma unroll
            for (int mt = 0; mt < 4; mt++) {
                uint32_t ad = asBase + ((mt * 16 + laneRow) * 72 + colElem) * 2;
                ldsm_x4(a[mt][0], a[mt][1], a[mt][2], a[mt][3], ad);
            }
#pragma unroll
            for (int h = 0; h < 2; h++) {
                uint32_t bd = bsBase + ((w * 32 + h * 16 + laneRow) * 72 + colElem) * 2;
                ldsm_x4(b[2 * h][0], b[2 * h + 1][0], b[2 * h][1], b[2 * h + 1][1], bd);
            }
#pragma unroll
            for (int mt = 0; mt < 4; mt++)
#pragma unroll
                for (int nt = 0; nt < 4; nt++) mma16816(acc[mt][nt], a[mt], b[nt]);
        }
        __syncthreads();
    }
    // --- write split-K partials as int16 (each partial exact in [-256,256]) ---
    short* op = g_simp + ((size_t)(kc * F_ + f) * B_) * V_;
#pragma unroll
    for (int mt = 0; mt < 4; mt++) {
        int r = mt * 16 + g;
#pragma unroll
        for (int nt = 0; nt < 4; nt++) {
            int c = w * 32 + nt * 8 + 2 * t;
            *(short2*)&op[(size_t)r * V_ + c] =
                make_short2((short)(int)acc[mt][nt][0], (short)(int)acc[mt][nt][1]);
            *(short2*)&op[(size_t)(r + 8) * V_ + c] =
                make_short2((short)(int)acc[mt][nt][2], (short)(int)acc[mt][nt][3]);
        }
    }
}

// ---------------- reduce int16 partials: 2 threads/element + shfl ----------------
__global__ void k_reduce() {
    int gid = blockIdx.x * blockDim.x + threadIdx.x;    // 131072 threads
    int i = gid >> 1;                                   // element 0..65535
    int half = gid & 1;
    int s = 0;
#pragma unroll
    for (int j = 0; j < KCH / 2; j++)
        s += (int)g_simp[(size_t)(half * (KCH / 2) + j) * (F_ * B_ * V_) + i];
    s += __shfl_xor_sync(0xffffffffu, s, 1);            // pair lanes 2k / 2k+1
    if (half == 0) {
        g_sim[i] = (float)s;                            // exact (|s| <= 16384)
        g_Ah[i] = __float2bfloat16((float)(s & ~127));  // multiple of 128 -> exact bf16
        g_Al[i] = __float2bfloat16((float)(s & 127));   // 0..127 -> exact bf16
    }
}

// ---------------- stage 3: est = sign( sum_v sim * cbD ) ----------------
__global__ void __launch_bounds__(256) k_update() {
    __shared__ __align__(16) __nv_bfloat16 Bs[128 * 72];
    __shared__ __align__(16) __nv_bfloat16 Ahs[64 * 72];
    __shared__ __align__(16) __nv_bfloat16 Als[64 * 72];
    const int dt = blockIdx.x, f = blockIdx.y;
    const int d0 = dt * 128;
    const int tid = threadIdx.x;
    const int w = tid >> 5, lane = tid & 31, g = lane >> 2, t = lane & 3;
    const int arow = tid >> 2, aseg = tid & 3;
    const int dB = tid >> 3, chB = tid & 7;

    const uint32_t ahBase = (uint32_t)__cvta_generic_to_shared(Ahs);
    const uint32_t alBase = (uint32_t)__cvta_generic_to_shared(Als);
    const uint32_t bsBase = (uint32_t)__cvta_generic_to_shared(Bs);
    const int laneRow  = lane & 15;
    const int laneColH = (lane >> 4) & 1;

    float acc[4][2][4];
#pragma unroll
    for (int mt = 0; mt < 4; mt++)
#pragma unroll
        for (int nt = 0; nt < 2; nt++)
#pragma unroll
            for (int j = 0; j < 4; j++) acc[mt][nt][j] = 0.f;

    uint4 h0, h1, l0, l1;
    uint4 rB[4];
    {
        const int vv = aseg * 16;
        h0 = *(const uint4*)(g_Ah + ((size_t)f * B_ + arow) * V_ + vv);
        h1 = *(const uint4*)(g_Ah + ((size_t)f * B_ + arow) * V_ + vv + 8);
        l0 = *(const uint4*)(g_Al + ((size_t)f * B_ + arow) * V_ + vv);
        l1 = *(const uint4*)(g_Al + ((size_t)f * B_ + arow) * V_ + vv + 8);
#pragma unroll
        for (int p = 0; p < 4; p++) {
            int dl = p * 32 + dB;
            rB[p] = *(const uint4*)(g_cbD + ((size_t)(f * D_ + d0 + dl)) * V_ + chB * 8);
        }
    }

    for (int vs = 0; vs < 4; vs++) {
        {
            uint4* ah = (uint4*)((uint32_t*)Ahs + arow * 36 + aseg * 8);
            uint4* al = (uint4*)((uint32_t*)Als + arow * 36 + aseg * 8);
            ah[0] = h0; ah[1] = h1;
            al[0] = l0; al[1] = l1;
#pragma unroll
            for (int p = 0; p < 4; p++)
                *(uint4*)((uint32_t*)Bs + (p * 32 + dB) * 36 + chB * 4) = rB[p];
        }
        __syncthreads();

        if (vs + 1 < 4) {
            const int v0n = (vs + 1) * 64;
            const int vv = v0n + aseg * 16;
            h0 = *(const uint4*)(g_Ah + ((size_t)f * B_ + arow) * V_ + vv);
            h1 = *(const uint4*)(g_Ah + ((size_t)f * B_ + arow) * V_ + vv + 8);
            l0 = *(const uint4*)(g_Al + ((size_t)f * B_ + arow) * V_ + vv);
            l1 = *(const uint4*)(g_Al + ((size_t)f * B_ + arow) * V_ + vv + 8);
#pragma unroll
            for (int p = 0; p < 4; p++) {
                int dl = p * 32 + dB;
                rB[p] = *(const uint4*)(g_cbD + ((size_t)(f * D_ + d0 + dl)) * V_ + v0n + chB * 8);
            }
        }

#pragma unroll
        for (int k16 = 0; k16 < 4; k16++) {
            const int colElem = k16 * 16 + laneColH * 8;
            uint32_t fa[4][4], fl[4][4], b[2][2];
#pragma unroll
            for (int mt = 0; mt < 4; mt++) {
                uint32_t adh = ahBase + ((mt * 16 + laneRow) * 72 + colElem) * 2;
                uint32_t adl = alBase + ((mt * 16 + laneRow) * 72 + colElem) * 2;
                ldsm_x4(fa[mt][0], fa[mt][1], fa[mt][2], fa[mt][3], adh);
                ldsm_x4(fl[mt][0], fl[mt][1], fl[mt][2], fl[mt][3], adl);
            }
            {
                uint32_t bd = bsBase + ((w * 16 + laneRow) * 72 + colElem) * 2;
                ldsm_x4(b[0][0], b[1][0], b[0][1], b[1][1], bd);
            }
#pragma unroll
            for (int mt = 0; mt < 4; mt++)
#pragma unroll
                for (int nt = 0; nt < 2; nt++) {
                    mma16816(acc[mt][nt], fa[mt], b[nt]);
                    mma16816(acc[mt][nt], fl[mt], b[nt]);
                }
        }
        __syncthreads();
    }
#pragma unroll
    for (int mt = 0; mt < 4; mt++) {
        int r = mt * 16 + g;
#pragma unroll
        for (int nt = 0; nt < 2; nt++) {
            int d = d0 + w * 16 + nt * 8 + 2 * t;
            uint32_t s0 = __float_as_uint(acc[mt][nt][0]);
            uint32_t s1 = __float_as_uint(acc[mt][nt][1]);
            uint32_t s2 = __float_as_uint(acc[mt][nt][2]);
            uint32_t s3 = __float_as_uint(acc[mt][nt][3]);
            uint32_t w0 = 0x3F803F80u | ((s0 >> 16) & 0x8000u) | (s1 & 0x80000000u);
            uint32_t w1 = 0x3F803F80u | ((s2 >> 16) & 0x8000u) | (s3 & 0x80000000u);
            ((uint32_t*)g_est_bf)[(((size_t)r * F_ + f) * D_ + d) >> 1] = w0;
            ((uint32_t*)g_est_bf)[(((size_t)(r + 8) * F_ + f) * D_ + d) >> 1] = w1;
        }
    }
}

// ---------------- outputs: est emit + outcome in ONE launch ----------------
#define EMIT_BLOCKS ((B_*F_*D_/2 + 255) / 256)     // 8192
__global__ void k_out(float* __restrict__ out, int do_outcome) {
    int blk = blockIdx.x;
    if (blk < EMIT_BLOCKS) {
        int i = blk * 256 + threadIdx.x;
        if (i < B_ * F_ * D_ / 2) {
            uint32_t w = ((const uint32_t*)g_est_bf)[i];
            float2 o;
            o.x = (w & 0x8000u) ? -1.f : 1.f;
            o.y = (w & 0x80000000u) ? -1.f : 1.f;
            ((float2*)out)[i] = o;
        }
    } else if (do_outcome) {
        int warp = (blk - EMIT_BLOCKS) * 8 + (threadIdx.x >> 5);
        int lane = threadIdx.x & 31;
        if (warp >= B_ * F_) return;
        int b = warp >> 2, f = warp & 3;
        const float* s = g_sim + ((size_t)(f * B_ + b)) * V_;
        float best = -1.f; int bi = 0;
#pragma unroll
        for (int j = 0; j < 8; j++) {
            int v = j * 32 + lane;
            float a = fabsf(s[v]);
            if (a > best) { best = a; bi = v; }
        }
#pragma unroll
        for (int off = 16; off; off >>= 1) {
            float ob = __shfl_down_sync(0xffffffffu, best, off);
            int   oi = __shfl_down_sync(0xffffffffu, bi, off);
            if (ob > best || (ob == best && oi < bi)) { best = ob; bi = oi; }
        }
        if (lane == 0) out[(size_t)B_ * F_ * D_ + warp] = (float)bi;
    }
}

// ---------------- host launch ----------------
extern "C" void kernel_launch(void* const* d_in, const int* in_sizes, int n_in,
                              void* d_out, int out_size) {
    const float *input = nullptr, *est0 = nullptr, *cb = nullptr;
    for (int i = 0; i < n_in; i++) {
        if      (in_sizes[i] == B_ * D_)        input = (const float*)d_in[i];
        else if (in_sizes[i] == B_ * F_ * D_)   est0  = (const float*)d_in[i];
        else if (in_sizes[i] == F_ * V_ * D_)   cb    = (const float*)d_in[i];
    }
    if (!input && n_in > 0) input = (const float*)d_in[0];
    if (!est0  && n_in > 1) est0  = (const float*)d_in[1];
    if (!cb    && n_in > 2) cb    = (const float*)d_in[2];

    k_signs<<<(NPAIRS_IN + NPAIRS_EST + 255) / 256, 256>>>(input, est0);
    k_cb<<<dim3(D_ / 32, V_ / 32, F_), 256>>>(cb);
    k_nop<<<1, 32>>>();                               // pads launch order: #4 = k_sim

    for (int it = 0; it < ITERS_; it++) {
        k_sim<<<dim3(KCH, F_), 256>>>(0);
        k_reduce<<<512, 256>>>();
        k_update<<<dim3(D_ / 128, F_), 256>>>();
    }
    // final similarity on converged estimates
    k_sim<<<dim3(KCH, F_), 256>>>(1);
    k_reduce<<<512, 256>>>();

    float* out = (float*)d_out;
    int do_outcome = (out_size >= B_ * F_ * D_ + B_ * F_) ? 1 : 0;
    int nblk = EMIT_BLOCKS + (do_outcome ? 32 : 0);
    k_out<<<nblk, 256>>>(out, do_outcome);
}